// round 2
// baseline (speedup 1.0000x reference)
#include <cuda_runtime.h>

#define SEQ   96
#define PRED  16
#define HID   64
#define FEAT  7
#define BPB   4               // batches per block
#define NBLK  128             // 512/4
#define NTHR  512
#define WIN   (SEQ + PRED)

typedef unsigned long long ull;

static __device__ __forceinline__ ull pack2(float a, float b){
    ull r; asm("mov.b64 %0, {%1, %2};" : "=l"(r) : "f"(a), "f"(b)); return r;
}
static __device__ __forceinline__ void unpack2(ull v, float &a, float &b){
    asm("mov.b64 {%0, %1}, %2;" : "=f"(a), "=f"(b) : "l"(v));
}
// d = a*b + d, packed f32x2 (Blackwell FFMA2), exact fp32 per lane
static __device__ __forceinline__ void ffma2(ull &d, ull a, ull b){
    asm("fma.rn.f32x2 %0, %1, %2, %0;" : "+l"(d) : "l"(a), "l"(b));
}

// s=1 -> sigmoid(x), s=2 -> tanh(x):  act = s/(1+exp(-s*x)) - (s-1)
static __device__ __forceinline__ float act(float x, float s, float sm1){
    float e = __expf(-s * x);
    return __fdividef(s, 1.0f + e) - sm1;
}
static __device__ __forceinline__ float tanhf_fast(float x){
    float e = __expf(-2.0f * x);
    return __fdividef(2.0f, 1.0f + e) - 1.0f;
}

__global__ void __launch_bounds__(NTHR, 1)
lstm_ar_kernel(const float* __restrict__ x,
               const float* __restrict__ W_ih,
               const float* __restrict__ W_hh,
               const float* __restrict__ b_ih,
               const float* __restrict__ b_hh,
               const float* __restrict__ fc_W,
               const float* __restrict__ fc_b,
               float* __restrict__ out)
{
    // sliding input window: [t][feat][b]  (12.5 KB)
    __shared__ float sh_xw[WIN * FEAT * BPB];
    // hidden state, double-buffered: [buf][col][b]
    __shared__ float h_sh[2][HID * BPB];
    __shared__ float sh_fcW[FEAT * HID];
    __shared__ float sh_fcb[FEAT];

    const int tid  = threadIdx.x;
    const int lane = tid & 31;
    const int half = tid & 1;          // K-split half (cols 0-31 / 32-63)
    const int r    = tid >> 1;         // 0..255: r = j*4 + g
    const int j    = r >> 2;           // hidden unit 0..63
    const int g    = r & 3;            // gate 0..3 (i,f,g,o)
    const int wrow = g * HID + j;      // row in W_ih/W_hh/b
    const int b0   = blockIdx.x * BPB;
    const bool leader = (lane & 7) == 0;   // g==0, half==0 lane of this unit
    const int base = lane & ~7;            // first lane of this unit's 8-lane group

    // ---------------- one-time init ----------------
    for (int i = tid; i < SEQ * FEAT * BPB; i += NTHR){
        int b  = i & 3;
        int q  = i >> 2;
        int f  = q % FEAT;
        int t  = q / FEAT;
        sh_xw[(t * FEAT + f) * BPB + b] =
            x[(size_t)(b0 + b) * SEQ * FEAT + t * FEAT + f];
    }
    for (int i = tid; i < FEAT * HID; i += NTHR) sh_fcW[i] = fc_W[i];
    if (tid < FEAT) sh_fcb[tid] = fc_b[tid];
    {
        float* hz = &h_sh[0][0];
        for (int i = tid; i < 2 * HID * BPB; i += NTHR) hz[i] = 0.0f;
    }

    // W_hh row slice for this thread: cols [half*32, half*32+32), splatted f32x2
    ull whh2[32];
    {
        const float4* wr = reinterpret_cast<const float4*>(
            W_hh + (size_t)wrow * HID + half * 32);
        #pragma unroll
        for (int q = 0; q < 8; q++){
            float4 w = wr[q];
            whh2[4*q+0] = pack2(w.x, w.x);
            whh2[4*q+1] = pack2(w.y, w.y);
            whh2[4*q+2] = pack2(w.z, w.z);
            whh2[4*q+3] = pack2(w.w, w.w);
        }
    }
    // Input projection split: half0 -> feats 0..3, half1 -> feats 3..6 (weight 0 on feat 3)
    ull wih2[4];
    #pragma unroll
    for (int kk = 0; kk < 4; kk++){
        int f = half * 3 + kk;
        float w = (half && kk == 0) ? 0.0f : W_ih[wrow * FEAT + f];
        wih2[kk] = pack2(w, w);
    }
    const float bias  = half ? 0.0f : (b_ih[wrow] + b_hh[wrow]);
    const ull   bias2 = pack2(bias, bias);

    const float s_act = (g == 2) ? 2.0f : 1.0f;   // cell gate uses tanh
    const float s_m1  = s_act - 1.0f;

    float c0 = 0.f, c1 = 0.f, c2 = 0.f, c3 = 0.f;   // leader-owned cell state
    int p = 0;

    __syncthreads();

    // ---------------- 16 AR iterations x 96 recurrent steps ----------------
    for (int k = 0; k < PRED; k++){
        for (int t = 0; t < SEQ; t++){
            // ---- gate pre-activation: partial dot over this thread's 32 cols ----
            ull a01 = bias2, a23 = bias2;
            const ulonglong2* xq =
                reinterpret_cast<const ulonglong2*>(&sh_xw[(k + t) * FEAT * BPB]) + half * 3;
            #pragma unroll
            for (int kk = 0; kk < 4; kk++){
                ulonglong2 xx = xq[kk];
                ffma2(a01, xx.x, wih2[kk]);
                ffma2(a23, xx.y, wih2[kk]);
            }
            const ulonglong2* hp =
                reinterpret_cast<const ulonglong2*>(&h_sh[p][0]) + half * 32;
            #pragma unroll
            for (int cc = 0; cc < 32; cc++){
                ulonglong2 hh = hp[cc];
                ffma2(a01, hh.x, whh2[cc]);
                ffma2(a23, hh.y, whh2[cc]);
            }
            float v0, v1, v2, v3;
            unpack2(a01, v0, v1);
            unpack2(a23, v2, v3);
            // combine K-halves (partner = lane^1)
            v0 += __shfl_xor_sync(0xffffffffu, v0, 1);
            v1 += __shfl_xor_sync(0xffffffffu, v1, 1);
            v2 += __shfl_xor_sync(0xffffffffu, v2, 1);
            v3 += __shfl_xor_sync(0xffffffffu, v3, 1);
            // activation on even (half0) lanes only
            if (!half){
                v0 = act(v0, s_act, s_m1);
                v1 = act(v1, s_act, s_m1);
                v2 = act(v2, s_act, s_m1);
                v3 = act(v3, s_act, s_m1);
            }
            // gather f/g/o gate activations to the leader lane (even-lane sources)
            float f0 = __shfl_sync(0xffffffffu, v0, base + 2);
            float f1 = __shfl_sync(0xffffffffu, v1, base + 2);
            float f2 = __shfl_sync(0xffffffffu, v2, base + 2);
            float f3 = __shfl_sync(0xffffffffu, v3, base + 2);
            float q0 = __shfl_sync(0xffffffffu, v0, base + 4);
            float q1 = __shfl_sync(0xffffffffu, v1, base + 4);
            float q2 = __shfl_sync(0xffffffffu, v2, base + 4);
            float q3 = __shfl_sync(0xffffffffu, v3, base + 4);
            float o0 = __shfl_sync(0xffffffffu, v0, base + 6);
            float o1 = __shfl_sync(0xffffffffu, v1, base + 6);
            float o2 = __shfl_sync(0xffffffffu, v2, base + 6);
            float o3 = __shfl_sync(0xffffffffu, v3, base + 6);
            if (leader){
                // own v = activated input gate i
                c0 = f0 * c0 + v0 * q0;
                c1 = f1 * c1 + v1 * q1;
                c2 = f2 * c2 + v2 * q2;
                c3 = f3 * c3 + v3 * q3;
                float4 hv = make_float4(o0 * tanhf_fast(c0),
                                        o1 * tanhf_fast(c1),
                                        o2 * tanhf_fast(c2),
                                        o3 * tanhf_fast(c3));
                *reinterpret_cast<float4*>(&h_sh[p ^ 1][j * 4]) = hv;
            }
            __syncthreads();
            p ^= 1;
        }

        // ---- fc head: pred = h @ fc_W^T + fc_b; append to window; emit ----
        if (tid < FEAT * BPB){
            int b = tid / FEAT;
            int o = tid - b * FEAT;
            float acc = sh_fcb[o];
            #pragma unroll
            for (int jj = 0; jj < HID; jj++)
                acc += h_sh[p][jj * BPB + b] * sh_fcW[o * HID + jj];
            out[(size_t)(b0 + b) * PRED * FEAT + k * FEAT + o] = acc;
            sh_xw[((SEQ + k) * FEAT + o) * BPB + b] = acc;
        }
        __syncthreads();
    }
}

extern "C" void kernel_launch(void* const* d_in, const int* in_sizes, int n_in,
                              void* d_out, int out_size)
{
    const float* x    = (const float*)d_in[0];
    const float* W_ih = (const float*)d_in[1];
    const float* W_hh = (const float*)d_in[2];
    const float* b_ih = (const float*)d_in[3];
    const float* b_hh = (const float*)d_in[4];
    const float* fc_W = (const float*)d_in[5];
    const float* fc_b = (const float*)d_in[6];
    float* out = (float*)d_out;

    lstm_ar_kernel<<<NBLK, NTHR>>>(x, W_ih, W_hh, b_ih, b_hh, fc_W, fc_b, out);
}

// round 3
// speedup vs baseline: 2.0053x; 2.0053x over previous
#include <cuda_runtime.h>

#define SEQ   96
#define PRED  16
#define HID   64
#define FEAT  7
#define BPB   2               // batches per block
#define NBLK  256             // 512/2
#define NTHR  256
#define WIN   (SEQ + PRED)

typedef unsigned long long ull;

static __device__ __forceinline__ ull pack2(float a, float b){
    ull r; asm("mov.b64 %0, {%1, %2};" : "=l"(r) : "f"(a), "f"(b)); return r;
}
static __device__ __forceinline__ void unpack2(ull v, float &a, float &b){
    asm("mov.b64 {%0, %1}, %2;" : "=f"(a), "=f"(b) : "l"(v));
}
// d = a*b + d, packed f32x2 (Blackwell FFMA2), exact fp32 per lane
static __device__ __forceinline__ void ffma2(ull &d, ull a, ull b){
    asm("fma.rn.f32x2 %0, %1, %2, %0;" : "+l"(d) : "l"(a), "l"(b));
}

// s=1 -> sigmoid(x), s=2 -> tanh(x):  act = s/(1+exp(-s*x)) - (s-1)
static __device__ __forceinline__ float act(float x, float s, float sm1){
    float e = __expf(-s * x);
    return __fdividef(s, 1.0f + e) - sm1;
}
static __device__ __forceinline__ float tanhf_fast(float x){
    float e = __expf(-2.0f * x);
    return __fdividef(2.0f, 1.0f + e) - 1.0f;
}

__global__ void __launch_bounds__(NTHR, 2)
lstm_ar_kernel(const float* __restrict__ x,
               const float* __restrict__ W_ih,
               const float* __restrict__ W_hh,
               const float* __restrict__ b_ih,
               const float* __restrict__ b_hh,
               const float* __restrict__ fc_W,
               const float* __restrict__ fc_b,
               float* __restrict__ out)
{
    // sliding input window: [t][feat][b]  (6.3 KB)
    __shared__ float sh_xw[WIN * FEAT * BPB];
    // hidden state, double-buffered: [buf][b][col]  (batch-major, 16B-aligned rows)
    __shared__ float h_sh[2][BPB * HID];
    // gate activations: [g][j][b]  (index = 2*wrow + b)
    __shared__ float sgates[4 * HID * BPB];
    __shared__ float sh_fcW[FEAT * HID];
    __shared__ float sh_fcb[FEAT];

    const int tid  = threadIdx.x;      // == wrow = g*64 + j  (phase-A identity)
    const int g    = tid >> 6;         // gate 0..3 (i,f,g,o)
    const int b0   = blockIdx.x * BPB;

    // ---------------- one-time init ----------------
    for (int i = tid; i < SEQ * FEAT * BPB; i += NTHR){
        int b  = i & 1;
        int q  = i >> 1;
        int f  = q % FEAT;
        int t  = q / FEAT;
        sh_xw[(t * FEAT + f) * BPB + b] =
            x[(size_t)(b0 + b) * SEQ * FEAT + t * FEAT + f];
    }
    for (int i = tid; i < FEAT * HID; i += NTHR) sh_fcW[i] = fc_W[i];
    if (tid < FEAT) sh_fcb[tid] = fc_b[tid];
    {
        float* hz = &h_sh[0][0];
        for (int i = tid; i < 2 * BPB * HID; i += NTHR) hz[i] = 0.0f;
    }

    // W_hh row for this thread's gate output, as natural column-pairs (no splat):
    // whh2[c] = (W[2c], W[2c+1]) — 32 u64 regs.
    ull whh2[HID / 2];
    {
        const ull* wr = reinterpret_cast<const ull*>(W_hh + (size_t)tid * HID);
        #pragma unroll
        for (int c = 0; c < HID / 2; c++) whh2[c] = wr[c];
    }
    float wih[FEAT];
    #pragma unroll
    for (int f = 0; f < FEAT; f++) wih[f] = W_ih[tid * FEAT + f];
    const float bias = b_ih[tid] + b_hh[tid];

    const float s_act = (g == 2) ? 2.0f : 1.0f;   // cell gate uses tanh
    const float s_m1  = s_act - 1.0f;

    // phase-B identity: thread tid<128 owns (batch bB, hidden unit jB)
    const int bB = tid & 1;
    const int jB = tid >> 1;
    float c_reg = 0.0f;
    int p = 0;

    __syncthreads();

    // ---------------- 16 AR iterations x 96 recurrent steps ----------------
    for (int k = 0; k < PRED; k++){
        for (int t = 0; t < SEQ; t++){
            // ---- phase A: pre-activation, f32x2 acc = (even-col, odd-col) partials ----
            ull acc0 = pack2(bias, 0.0f);   // batch 0
            ull acc1 = pack2(0.0f, 0.0f);   // batch 1
            const ulonglong2* h0 =
                reinterpret_cast<const ulonglong2*>(&h_sh[p][0]);
            const ulonglong2* h1 =
                reinterpret_cast<const ulonglong2*>(&h_sh[p][HID]);
            #pragma unroll
            for (int c = 0; c < HID / 4; c++){
                ulonglong2 u0 = h0[c];             // broadcast LDS.128: cols 4c..4c+3, b0
                ffma2(acc0, u0.x, whh2[2*c]);
                ffma2(acc0, u0.y, whh2[2*c+1]);
                ulonglong2 u1 = h1[c];             // same cols, b1
                ffma2(acc1, u1.x, whh2[2*c]);
                ffma2(acc1, u1.y, whh2[2*c+1]);
            }
            float e0, o0, e1, o1;
            unpack2(acc0, e0, o0);
            unpack2(acc1, e1, o1);
            float v0 = e0 + o0;
            float v1 = e1 + o1 + bias;
            // input-feature projection (scalar, 7 feats)
            const float2* xp =
                reinterpret_cast<const float2*>(&sh_xw[(k + t) * FEAT * BPB]);
            #pragma unroll
            for (int f = 0; f < FEAT; f++){
                float2 xx = xp[f];                 // (x_f[b0], x_f[b1])
                v0 = fmaf(wih[f], xx.x, v0);
                v1 = fmaf(wih[f], xx.y, v1);
            }
            v0 = act(v0, s_act, s_m1);
            v1 = act(v1, s_act, s_m1);
            *reinterpret_cast<float2*>(&sgates[2 * tid]) = make_float2(v0, v1);
            __syncthreads();

            // ---- phase B: cell update for (bB, jB), threads 0..127 ----
            if (tid < HID * BPB){
                const int off = (jB << 1) + bB;
                float gi = sgates[          off];
                float gf = sgates[1 * 128 + off];
                float gg = sgates[2 * 128 + off];
                float go = sgates[3 * 128 + off];
                c_reg = gf * c_reg + gi * gg;
                h_sh[p ^ 1][bB * HID + jB] = go * tanhf_fast(c_reg);
            }
            __syncthreads();
            p ^= 1;
        }

        // ---- fc head: pred = h @ fc_W^T + fc_b; append to window; emit ----
        if (tid < FEAT * BPB){
            int b = tid / FEAT;
            int o = tid - b * FEAT;
            float acc = sh_fcb[o];
            #pragma unroll
            for (int jj = 0; jj < HID; jj++)
                acc += h_sh[p][b * HID + jj] * sh_fcW[o * HID + jj];
            out[(size_t)(b0 + b) * PRED * FEAT + k * FEAT + o] = acc;
            sh_xw[((SEQ + k) * FEAT + o) * BPB + b] = acc;
        }
        __syncthreads();
    }
}

extern "C" void kernel_launch(void* const* d_in, const int* in_sizes, int n_in,
                              void* d_out, int out_size)
{
    const float* x    = (const float*)d_in[0];
    const float* W_ih = (const float*)d_in[1];
    const float* W_hh = (const float*)d_in[2];
    const float* b_ih = (const float*)d_in[3];
    const float* b_hh = (const float*)d_in[4];
    const float* fc_W = (const float*)d_in[5];
    const float* fc_b = (const float*)d_in[6];
    float* out = (float*)d_out;

    lstm_ar_kernel<<<NBLK, NTHR>>>(x, W_ih, W_hh, b_ih, b_hh, fc_W, fc_b, out);
}

// round 4
// speedup vs baseline: 2.4367x; 1.2152x over previous
#include <cuda_runtime.h>

#define SEQ   96
#define PRED  16
#define HID   64
#define FEAT  7
#define BPB   2               // batches per block
#define NBLK  256             // 512/2
#define NTHR  128
#define WIN   (SEQ + PRED)

typedef unsigned long long ull;

static __device__ __forceinline__ ull pack2(float a, float b){
    ull r; asm("mov.b64 %0, {%1, %2};" : "=l"(r) : "f"(a), "f"(b)); return r;
}
static __device__ __forceinline__ void unpack2(ull v, float &a, float &b){
    asm("mov.b64 {%0, %1}, %2;" : "=f"(a), "=f"(b) : "l"(v));
}
// d = a*b + d, packed f32x2 (Blackwell FFMA2), exact fp32 per lane
static __device__ __forceinline__ void ffma2(ull &d, ull a, ull b){
    asm("fma.rn.f32x2 %0, %1, %2, %0;" : "+l"(d) : "l"(a), "l"(b));
}

static __device__ __forceinline__ float sigmoid_fast(float x){
    float e = __expf(-x);
    return __fdividef(1.0f, 1.0f + e);
}
static __device__ __forceinline__ float tanhf_fast(float x){
    float e = __expf(-2.0f * x);
    return __fdividef(2.0f, 1.0f + e) - 1.0f;
}
// s=1 -> sigmoid, s=2 -> tanh
static __device__ __forceinline__ float act(float x, float s, float sm1){
    float e = __expf(-s * x);
    return __fdividef(s, 1.0f + e) - sm1;
}

__global__ void __launch_bounds__(NTHR, 2)
lstm_ar_kernel(const float* __restrict__ x,
               const float* __restrict__ W_ih,
               const float* __restrict__ W_hh,
               const float* __restrict__ b_ih,
               const float* __restrict__ b_hh,
               const float* __restrict__ fc_W,
               const float* __restrict__ fc_b,
               float* __restrict__ out)
{
    // sliding input window: [t][feat][b]  float2-friendly
    __shared__ float sh_xw[WIN * FEAT * BPB];
    // hidden state, double-buffered: [buf][b][col]
    __shared__ float h_sh[2][BPB * HID];
    // i*g exchange: one float2 (b0,b1) per hidden unit
    __shared__ float2 sh_ig[HID];
    __shared__ float sh_fcW[FEAT * HID];
    __shared__ float sh_fcb[FEAT];

    const int tid = threadIdx.x;           // 0..127
    const int b0  = blockIdx.x * BPB;
    const int r0  = tid;                   // row A: gate 0 (i) or 1 (f)
    const int r1  = tid + 128;             // row B: gate 2 (g) or 3 (o)
    const bool hi = (tid >= 64);           // hi threads own (f,o) + cell state
    const int u   = tid & 63;              // hidden unit

    // ---------------- one-time init ----------------
    for (int i = tid; i < SEQ * FEAT * BPB; i += NTHR){
        int b = i & 1;
        int q = i >> 1;
        int f = q % FEAT;
        int t = q / FEAT;
        sh_xw[(t * FEAT + f) * BPB + b] =
            x[(size_t)(b0 + b) * SEQ * FEAT + t * FEAT + f];
    }
    for (int i = tid; i < FEAT * HID; i += NTHR) sh_fcW[i] = fc_W[i];
    if (tid < FEAT) sh_fcb[tid] = fc_b[tid];
    {
        float* hz = &h_sh[0][0];
        for (int i = tid; i < 2 * BPB * HID; i += NTHR) hz[i] = 0.0f;
    }

    // W_hh rows for this thread's two gate outputs, as natural column-pairs:
    // whh*[c] = (W[2c], W[2c+1]) read directly as u64 — 2 x 32 u64 regs.
    ull whhA[HID / 2], whhB[HID / 2];
    {
        const ull* wa = reinterpret_cast<const ull*>(W_hh + (size_t)r0 * HID);
        const ull* wb = reinterpret_cast<const ull*>(W_hh + (size_t)r1 * HID);
        #pragma unroll
        for (int c = 0; c < HID / 2; c++){ whhA[c] = wa[c]; whhB[c] = wb[c]; }
    }
    float wihA[FEAT], wihB[FEAT];
    #pragma unroll
    for (int f = 0; f < FEAT; f++){
        wihA[f] = W_ih[r0 * FEAT + f];
        wihB[f] = W_ih[r1 * FEAT + f];
    }
    const float biasA = b_ih[r0] + b_hh[r0];
    const float biasB = b_ih[r1] + b_hh[r1];

    // row A is gate 0/1 -> always sigmoid; row B: gate 2 (tanh) if !hi else gate 3 (sigmoid)
    const float sB  = hi ? 1.0f : 2.0f;
    const float sBm = sB - 1.0f;

    float c0 = 0.0f, c1 = 0.0f;   // cell state (hi threads), per batch
    int p = 0;

    __syncthreads();

    // ---------------- 16 AR iterations x 96 recurrent steps ----------------
    for (int k = 0; k < PRED; k++){
        for (int t = 0; t < SEQ; t++){
            // ---- gate pre-activations: 4 f32x2 accumulators (2 rows x 2 batches) ----
            ull aA0 = pack2(biasA, 0.0f);
            ull aA1 = pack2(0.0f, 0.0f);
            ull aB0 = pack2(biasB, 0.0f);
            ull aB1 = pack2(0.0f, 0.0f);
            const ulonglong2* h0 = reinterpret_cast<const ulonglong2*>(&h_sh[p][0]);
            const ulonglong2* h1 = reinterpret_cast<const ulonglong2*>(&h_sh[p][HID]);
            #pragma unroll
            for (int c = 0; c < HID / 4; c++){
                ulonglong2 u0 = h0[c];     // cols 4c..4c+3, batch 0 (broadcast LDS.128)
                ulonglong2 u1 = h1[c];     // same cols, batch 1
                ffma2(aA0, u0.x, whhA[2*c]);
                ffma2(aA0, u0.y, whhA[2*c+1]);
                ffma2(aB0, u0.x, whhB[2*c]);
                ffma2(aB0, u0.y, whhB[2*c+1]);
                ffma2(aA1, u1.x, whhA[2*c]);
                ffma2(aA1, u1.y, whhA[2*c+1]);
                ffma2(aB1, u1.x, whhB[2*c]);
                ffma2(aB1, u1.y, whhB[2*c+1]);
            }
            float e, o;
            float vA0, vA1, vB0, vB1;
            unpack2(aA0, e, o); vA0 = e + o;
            unpack2(aA1, e, o); vA1 = e + o + biasA;
            unpack2(aB0, e, o); vB0 = e + o;
            unpack2(aB1, e, o); vB1 = e + o + biasB;
            // input-feature projection
            const float2* xp =
                reinterpret_cast<const float2*>(&sh_xw[(k + t) * FEAT * BPB]);
            #pragma unroll
            for (int f = 0; f < FEAT; f++){
                float2 xx = xp[f];
                vA0 = fmaf(wihA[f], xx.x, vA0);
                vA1 = fmaf(wihA[f], xx.y, vA1);
                vB0 = fmaf(wihB[f], xx.x, vB0);
                vB1 = fmaf(wihB[f], xx.y, vB1);
            }
            // activations: A rows sigmoid; B rows tanh (lo) / sigmoid (hi)
            vA0 = sigmoid_fast(vA0);
            vA1 = sigmoid_fast(vA1);
            vB0 = act(vB0, sB, sBm);
            vB1 = act(vB1, sB, sBm);

            if (!hi){
                // lo thread: vA = i, vB = g  -> publish i*g
                sh_ig[u] = make_float2(vA0 * vB0, vA1 * vB1);
            }
            __syncthreads();
            if (hi){
                // hi thread: vA = f, vB = o; owns cell state of unit u
                float2 ig = sh_ig[u];
                c0 = fmaf(vA0, c0, ig.x);
                c1 = fmaf(vA1, c1, ig.y);
                h_sh[p ^ 1][      u] = vB0 * tanhf_fast(c0);
                h_sh[p ^ 1][HID + u] = vB1 * tanhf_fast(c1);
            }
            __syncthreads();
            p ^= 1;
        }

        // ---- fc head: pred = h @ fc_W^T + fc_b; append to window; emit ----
        if (tid < FEAT * BPB){
            int b = tid / FEAT;
            int o2 = tid - b * FEAT;
            float acc = sh_fcb[o2];
            #pragma unroll
            for (int jj = 0; jj < HID; jj++)
                acc += h_sh[p][b * HID + jj] * sh_fcW[o2 * HID + jj];
            out[(size_t)(b0 + b) * PRED * FEAT + k * FEAT + o2] = acc;
            sh_xw[((SEQ + k) * FEAT + o2) * BPB + b] = acc;
        }
        __syncthreads();
    }
}

extern "C" void kernel_launch(void* const* d_in, const int* in_sizes, int n_in,
                              void* d_out, int out_size)
{
    const float* x    = (const float*)d_in[0];
    const float* W_ih = (const float*)d_in[1];
    const float* W_hh = (const float*)d_in[2];
    const float* b_ih = (const float*)d_in[3];
    const float* b_hh = (const float*)d_in[4];
    const float* fc_W = (const float*)d_in[5];
    const float* fc_b = (const float*)d_in[6];
    float* out = (float*)d_out;

    lstm_ar_kernel<<<NBLK, NTHR>>>(x, W_ih, W_hh, b_ih, b_hh, fc_W, fc_b, out);
}